// round 10
// baseline (speedup 1.0000x reference)
#include <cuda_runtime.h>
#include <cuda_bf16.h>
#include <cstdint>

#define NCAT 20
#define NNUM 20
#define EMBD 32
#define HID  128
#define NMOD 50
#define NTHR 384            // 12 warps; warp w owns rows 16w..16w+15 of a 192-row tile
#define TROWS 192

typedef unsigned long long u64;
typedef unsigned int u32;

// ---------------- smem layout ----------------
#define BSTR  136                       // bf16 per BT row (272 B)
#define GSTR  68                        // u32 per staging row (conflict-free: 68%32=4)
#define OB    0                         // 6 * 128 * 272 = 208896 B
#define OSTH  208896                    // stgH 32 * 68 * 4 = 8704 B
#define OSTL  217600                    // stgL 8704 B
#define OD    226304                    // 384 * 4 = 1536 B
#define SMEM_REQ 227840                 // <= 232448

// ---------------- device scratch ----------------
__device__ float g_Tcat[NCAT * NMOD * HID];
__device__ float g_vnum[NNUM * HID];
__device__ float g_base[HID];
__device__ float g_d[3 * HID];
__device__ __align__(16) unsigned short g_B[6 * HID * BSTR];

// ---------------- helpers ----------------
__device__ __forceinline__ u64 dup2(float a) {
    u64 r; asm("mov.b64 %0,{%1,%1};" : "=l"(r) : "f"(a)); return r;
}
__device__ __forceinline__ float2 upk2(u64 v) {
    float2 f; asm("mov.b64 {%0,%1},%2;" : "=f"(f.x), "=f"(f.y) : "l"(v)); return f;
}
__device__ __forceinline__ u64 fma2(u64 a, u64 b, u64 c) {
    u64 d; asm("fma.rn.f32x2 %0,%1,%2,%3;" : "=l"(d) : "l"(a), "l"(b), "l"(c)); return d;
}
__device__ __forceinline__ u64 add2(u64 a, u64 b) {
    u64 d; asm("add.rn.f32x2 %0,%1,%2;" : "=l"(d) : "l"(a), "l"(b)); return d;
}
__device__ __forceinline__ u32 cvt_bf2(float hi_val, float lo_val) {
    u32 w; asm("cvt.rn.bf16x2.f32 %0,%1,%2;" : "=r"(w) : "f"(hi_val), "f"(lo_val)); return w;
}
__device__ __forceinline__ void split2(float c0, float c1, u32& hi, u32& lo) {
    hi = cvt_bf2(c1, c0);
    float e0 = c0 - __uint_as_float(hi << 16);
    float e1 = c1 - __uint_as_float(hi & 0xffff0000u);
    lo = cvt_bf2(e1, e0);
}

#define MMA(d, a, b0v, b1v) \
    asm volatile("mma.sync.aligned.m16n8k16.row.col.f32.bf16.bf16.f32 " \
        "{%0,%1,%2,%3},{%4,%5,%6,%7},{%8,%9},{%0,%1,%2,%3};" \
        : "+f"((d)[0]), "+f"((d)[1]), "+f"((d)[2]), "+f"((d)[3]) \
        : "r"((a)[0]), "r"((a)[1]), "r"((a)[2]), "r"((a)[3]), "r"(b0v), "r"(b1v))

// ---------------- precompute kernel ----------------
__global__ void pre_all_kernel(const float* __restrict__ emb,
                               const float* __restrict__ W_num, const float* __restrict__ b_num,
                               const float* __restrict__ W_in,  const float* __restrict__ b_in,
                               const float* __restrict__ W1,    const float* __restrict__ b1,
                               const float* __restrict__ W2,    const float* __restrict__ b2,
                               const float* __restrict__ ln_g,  const float* __restrict__ ln_b,
                               const float* __restrict__ W_out, const float* __restrict__ b_out) {
    const int b = blockIdx.x;
    const int j = threadIdx.x;
    if (b < NCAT * NMOD) {
        int fc = b, f = fc / NMOD;
        const float* e = emb + fc * EMBD;
        float s = 0.f;
#pragma unroll
        for (int k = 0; k < EMBD; k++) s += e[k] * W_in[(f * EMBD + k) * HID + j];
        g_Tcat[fc * HID + j] = s;
    } else if (b < NCAT * NMOD + 3 * HID) {
        int bx = b - NCAT * NMOD;
        int s = bx >> 7, k = bx & 127;
        float v;
        if (s == 2) {
            v = ln_g[HID + k] * W_out[k * HID + j];
        } else {
            const float* w1 = W1 + s * HID * 2 * HID + k * 2 * HID;
            const float* w2 = W2 + s * 2 * HID * HID;
            float acc = 0.f;
            for (int m = 0; m < 2 * HID; m++) acc += w1[m] * w2[m * HID + j];
            v = (s == 1) ? ln_g[k] * acc : acc;
        }
        __nv_bfloat16 h = __float2bfloat16(v);
        float rem = v - __bfloat162float(h);
        __nv_bfloat16 lo = __float2bfloat16(rem);
        g_B[(size_t)(s * 2 + 0) * HID * BSTR + j * BSTR + k] = *reinterpret_cast<unsigned short*>(&h);
        g_B[(size_t)(s * 2 + 1) * HID * BSTR + j * BSTR + k] = *reinterpret_cast<unsigned short*>(&lo);
    } else {
        for (int f = 0; f < NNUM; f++) {
            float s = 0.f;
#pragma unroll
            for (int k = 0; k < EMBD; k++)
                s += W_num[f * EMBD + k] * W_in[((NCAT + f) * EMBD + k) * HID + j];
            g_vnum[f * HID + j] = s;
        }
        float bb = b_in[j];
        for (int f = 0; f < NNUM; f++)
#pragma unroll
            for (int k = 0; k < EMBD; k++)
                bb += b_num[f * EMBD + k] * W_in[((NCAT + f) * EMBD + k) * HID + j];
        g_base[j] = bb;
        float d1 = b2[j];
        for (int m = 0; m < 2 * HID; m++) d1 += b1[m] * W2[m * HID + j];
        g_d[j] = d1;
        __shared__ float u[2 * HID];
        for (int m = j; m < 2 * HID; m += HID) {
            float s = 0.f;
            for (int k = 0; k < HID; k++)
                s += ln_b[k] * W1[HID * 2 * HID + k * 2 * HID + m];
            u[m] = s;
        }
        __syncthreads();
        float d2 = b2[HID + j];
        for (int m = 0; m < 2 * HID; m++)
            d2 += (u[m] + b1[2 * HID + m]) * W2[2 * HID * HID + m * HID + j];
        g_d[HID + j] = d2;
        float d3 = b_out[j];
        for (int k = 0; k < HID; k++) d3 += ln_b[HID + k] * W_out[k * HID + j];
        g_d[2 * HID + j] = d3;
    }
}

// ---------------- main fused kernel ----------------
__global__ __launch_bounds__(NTHR, 1)
void main_kernel(const float* __restrict__ x, float* __restrict__ out,
                 int nrows, int ntiles) {
    extern __shared__ __align__(16) char smem[];
    const int t = threadIdx.x;
    const int w = t >> 5;
    const int l = t & 31;
    const int q = l >> 2;
    const int m = l & 3;

    // copy BT matrices and bias vectors
    {
        const float4* src = (const float4*)g_B;
        float4* dst = (float4*)(smem + OB);
        for (int i = t; i < 208896 / 16; i += NTHR) dst[i] = src[i];
        float* dd = (float*)(smem + OD);
        for (int i = t; i < 3 * HID; i += NTHR) dd[i] = g_d[i];
    }
    __syncthreads();

    const unsigned short* BT = (const unsigned short*)(smem + OB);
    u32* stgH = (u32*)(smem + OSTH);
    u32* stgL = (u32*)(smem + OSTL);
    const float* dsm = (const float*)(smem + OD);

    const u64* Tc = (const u64*)g_Tcat;
    const u64* Vn = (const u64*)g_vnum;
    const u64* Bs = (const u64*)g_base;
    const int p    = t & 63;     // embed: col pair 2p,2p+1 (fixed per thread)
    const int slot = t >> 6;     // embed: row slot 0..5

    for (int tt = blockIdx.x; tt < ntiles; tt += gridDim.x) {
        const int row0 = tt * TROWS;

        // per-tile invariants for embed
        u64 vn[NNUM];
#pragma unroll
        for (int f = 0; f < NNUM; f++) vn[f] = __ldg(Vn + f * 64 + p);
        const u64 bb = __ldg(Bs + p);

        // ============ embed 6 chunks of 32 rows -> bf16 staging -> A fragments ============
        u32 AH[8][4], AL[8][4];
        for (int c = 0; c < 6; c++) {
            const int crow = row0 + 32 * c;
            for (int r = slot; r < 32; r += 6) {
                const float* xr = x + (size_t)min(crow + r, nrows - 1) * 40;
                u64 aA = bb, aB = 0ull;
#pragma unroll
                for (int f = 0; f < 10; f++) {
                    int ia = (int)xr[f];
                    int ib = (int)xr[10 + f];
                    aA = add2(aA, __ldg(Tc + (f * NMOD + ia) * 64 + p));
                    aB = add2(aB, __ldg(Tc + ((10 + f) * NMOD + ib) * 64 + p));
                }
#pragma unroll
                for (int f = 0; f < 10; f++) {
                    aA = fma2(vn[f], dup2(xr[NCAT + f]), aA);
                    aB = fma2(vn[10 + f], dup2(xr[NCAT + 10 + f]), aB);
                }
                float2 v = upk2(add2(aA, aB));
                u32 hi, lo;
                split2(v.x, v.y, hi, lo);
                stgH[r * GSTR + p] = hi;
                stgL[r * GSTR + p] = lo;
            }
            __syncthreads();
            // warps 2c, 2c+1 own this chunk's 32 rows: build A fragments (pure LDS)
            if ((w >> 1) == c) {
                const int rb = (w & 1) * 16 + q;
#pragma unroll
                for (int kt = 0; kt < 8; kt++) {
                    int i0 = 8 * kt + m;
                    AH[kt][0] = stgH[rb * GSTR + i0];
                    AH[kt][1] = stgH[(rb + 8) * GSTR + i0];
                    AH[kt][2] = stgH[rb * GSTR + i0 + 4];
                    AH[kt][3] = stgH[(rb + 8) * GSTR + i0 + 4];
                    AL[kt][0] = stgL[rb * GSTR + i0];
                    AL[kt][1] = stgL[(rb + 8) * GSTR + i0];
                    AL[kt][2] = stgL[rb * GSTR + i0 + 4];
                    AL[kt][3] = stgL[(rb + 8) * GSTR + i0 + 4];
                }
            }
            __syncthreads();
        }

        // ============ 3 MMA stages, warp-local (R8 structure) ============
        float D[16][4];
#pragma unroll 1
        for (int s = 0; s < 3; s++) {
#pragma unroll
            for (int nt = 0; nt < 16; nt++) {
                float2 bv = *(const float2*)&dsm[s * HID + nt * 8 + 2 * m];
                D[nt][0] = bv.x; D[nt][1] = bv.y; D[nt][2] = bv.x; D[nt][3] = bv.y;
            }
            const unsigned short* B0 = BT + (size_t)(s * 2) * HID * BSTR;
            const unsigned short* B1 = B0 + (size_t)HID * BSTR;
#pragma unroll
            for (int kt = 0; kt < 8; kt++) {
                const int koff = kt * 16 + 2 * m;
#pragma unroll
                for (int nt = 0; nt < 16; nt++) {
                    const u32* pb = (const u32*)(B0 + (nt * 8 + q) * BSTR + koff);
                    u32 b0 = pb[0], b1 = pb[4];
                    MMA(D[nt], AH[kt], b0, b1);
                    MMA(D[nt], AL[kt], b0, b1);
                }
#pragma unroll
                for (int nt = 0; nt < 16; nt++) {
                    const u32* pb = (const u32*)(B1 + (nt * 8 + q) * BSTR + koff);
                    u32 b0 = pb[0], b1 = pb[4];
                    MMA(D[nt], AH[kt], b0, b1);
                }
            }

            if (s < 2) {
                // ---- LayerNorm (rows q and q+8 of this warp's 16) ----
                float s1a = 0.f, s2a = 0.f, s1b = 0.f, s2b = 0.f;
#pragma unroll
                for (int nt = 0; nt < 16; nt++) {
                    s1a += D[nt][0] + D[nt][1];
                    s2a += D[nt][0] * D[nt][0] + D[nt][1] * D[nt][1];
                    s1b += D[nt][2] + D[nt][3];
                    s2b += D[nt][2] * D[nt][2] + D[nt][3] * D[nt][3];
                }
#pragma unroll
                for (int off = 1; off <= 2; off <<= 1) {
                    s1a += __shfl_xor_sync(0xffffffffu, s1a, off);
                    s2a += __shfl_xor_sync(0xffffffffu, s2a, off);
                    s1b += __shfl_xor_sync(0xffffffffu, s1b, off);
                    s2b += __shfl_xor_sync(0xffffffffu, s2b, off);
                }
                const float inv = 1.f / HID;
                float mua = s1a * inv, mub = s1b * inv;
                float rsa = rsqrtf(s2a * inv - mua * mua + 1e-5f);
                float rsb = rsqrtf(s2b * inv - mub * mub + 1e-5f);
                float nma = -mua * rsa, nmb = -mub * rsb;
#pragma unroll
                for (int kt = 0; kt < 8; kt++) {
                    int n0 = 2 * kt, n1 = 2 * kt + 1;
                    split2(D[n0][0] * rsa + nma, D[n0][1] * rsa + nma, AH[kt][0], AL[kt][0]);
                    split2(D[n0][2] * rsb + nmb, D[n0][3] * rsb + nmb, AH[kt][1], AL[kt][1]);
                    split2(D[n1][0] * rsa + nma, D[n1][1] * rsa + nma, AH[kt][2], AL[kt][2]);
                    split2(D[n1][2] * rsb + nmb, D[n1][3] * rsb + nmb, AH[kt][3], AL[kt][3]);
                }
            } else {
                // ---- final store ----
                int ra = row0 + 16 * w + q;
                int rb2 = ra + 8;
#pragma unroll
                for (int nt = 0; nt < 16; nt++) {
                    int col = nt * 8 + 2 * m;
                    if (ra < nrows)
                        *(float2*)&out[(size_t)ra * HID + col] = make_float2(D[nt][0], D[nt][1]);
                    if (rb2 < nrows)
                        *(float2*)&out[(size_t)rb2 * HID + col] = make_float2(D[nt][2], D[nt][3]);
                }
            }
        }
    }
}

// ---------------- launch ----------------
extern "C" void kernel_launch(void* const* d_in, const int* in_sizes, int n_in,
                              void* d_out, int out_size) {
    const float* x     = (const float*)d_in[0];
    const float* emb   = (const float*)d_in[1];
    const float* W_num = (const float*)d_in[2];
    const float* b_num = (const float*)d_in[3];
    const float* W_in  = (const float*)d_in[4];
    const float* b_in  = (const float*)d_in[5];
    const float* W1    = (const float*)d_in[6];
    const float* b1    = (const float*)d_in[7];
    const float* W2    = (const float*)d_in[8];
    const float* b2    = (const float*)d_in[9];
    const float* ln_g  = (const float*)d_in[10];
    const float* ln_b  = (const float*)d_in[11];
    const float* W_out = (const float*)d_in[12];
    const float* b_out = (const float*)d_in[13];
    float* out = (float*)d_out;

    const int nrows  = in_sizes[0] / 40;
    const int ntiles = (nrows + TROWS - 1) / TROWS;

    static int smem_set = 0;
    if (!smem_set) {
        cudaFuncSetAttribute(main_kernel, cudaFuncAttributeMaxDynamicSharedMemorySize,
                             SMEM_REQ);
        smem_set = 1;
    }

    pre_all_kernel<<<NCAT * NMOD + 3 * HID + 1, HID>>>(
        emb, W_num, b_num, W_in, b_in, W1, b1, W2, b2, ln_g, ln_b, W_out, b_out);
    main_kernel<<<148, NTHR, SMEM_REQ>>>(x, out, nrows, ntiles);
}

// round 11
// speedup vs baseline: 1.2521x; 1.2521x over previous
#include <cuda_runtime.h>
#include <cuda_bf16.h>
#include <cstdint>

#define NCAT 20
#define NNUM 20
#define EMBD 32
#define HID  128
#define NMOD 50
#define NTHR 256

typedef unsigned long long u64;
typedef unsigned int u32;

// ---------------- smem layout ----------------
#define BSTR  136                       // bf16 per BT row (272 B) — conflict-free MMA B loads
#define SSTR  132                       // f32 per staging row (528 B, float4-aligned)
#define OB    0                         // 6 * 128 * 272 = 208896 B
#define OST   208896                    // staging 32 * 132 * 4 = 16896 B
#define OD    225792                    // 384 * 4 = 1536 B
#define SMEM_REQ 227328

// ---------------- device scratch ----------------
__device__ float g_Tcat[NCAT * NMOD * HID];
__device__ float g_vnum[NNUM * HID];
__device__ float g_base[HID];
__device__ float g_d[3 * HID];
__device__ __align__(16) unsigned short g_B[6 * HID * BSTR];

// ---------------- helpers ----------------
__device__ __forceinline__ u64 dup2(float a) {
    u64 r; asm("mov.b64 %0,{%1,%1};" : "=l"(r) : "f"(a)); return r;
}
__device__ __forceinline__ float2 upk2(u64 v) {
    float2 f; asm("mov.b64 {%0,%1},%2;" : "=f"(f.x), "=f"(f.y) : "l"(v)); return f;
}
__device__ __forceinline__ u64 fma2(u64 a, u64 b, u64 c) {
    u64 d; asm("fma.rn.f32x2 %0,%1,%2,%3;" : "=l"(d) : "l"(a), "l"(b), "l"(c)); return d;
}
__device__ __forceinline__ u64 add2(u64 a, u64 b) {
    u64 d; asm("add.rn.f32x2 %0,%1,%2;" : "=l"(d) : "l"(a), "l"(b)); return d;
}
__device__ __forceinline__ u32 cvt_bf2(float hi_val, float lo_val) {
    u32 w; asm("cvt.rn.bf16x2.f32 %0,%1,%2;" : "=r"(w) : "f"(hi_val), "f"(lo_val)); return w;
}
__device__ __forceinline__ void split2(float c0, float c1, u32& hi, u32& lo) {
    hi = cvt_bf2(c1, c0);
    float e0 = c0 - __uint_as_float(hi << 16);
    float e1 = c1 - __uint_as_float(hi & 0xffff0000u);
    lo = cvt_bf2(e1, e0);
}

#define MMA(d, a, b0v, b1v) \
    asm volatile("mma.sync.aligned.m16n8k16.row.col.f32.bf16.bf16.f32 " \
        "{%0,%1,%2,%3},{%4,%5,%6,%7},{%8,%9},{%0,%1,%2,%3};" \
        : "+f"((d)[0]), "+f"((d)[1]), "+f"((d)[2]), "+f"((d)[3]) \
        : "r"((a)[0]), "r"((a)[1]), "r"((a)[2]), "r"((a)[3]), "r"(b0v), "r"(b1v))

// ---------------- precompute kernel ----------------
__global__ void pre_all_kernel(const float* __restrict__ emb,
                               const float* __restrict__ W_num, const float* __restrict__ b_num,
                               const float* __restrict__ W_in,  const float* __restrict__ b_in,
                               const float* __restrict__ W1,    const float* __restrict__ b1,
                               const float* __restrict__ W2,    const float* __restrict__ b2,
                               const float* __restrict__ ln_g,  const float* __restrict__ ln_b,
                               const float* __restrict__ W_out, const float* __restrict__ b_out) {
    const int b = blockIdx.x;
    const int j = threadIdx.x;
    if (b < NCAT * NMOD) {
        int fc = b, f = fc / NMOD;
        const float* e = emb + fc * EMBD;
        float s = 0.f;
#pragma unroll
        for (int k = 0; k < EMBD; k++) s += e[k] * W_in[(f * EMBD + k) * HID + j];
        g_Tcat[fc * HID + j] = s;
    } else if (b < NCAT * NMOD + 3 * HID) {
        int bx = b - NCAT * NMOD;
        int s = bx >> 7, k = bx & 127;
        float v;
        if (s == 2) {
            v = ln_g[HID + k] * W_out[k * HID + j];
        } else {
            const float* w1 = W1 + s * HID * 2 * HID + k * 2 * HID;
            const float* w2 = W2 + s * 2 * HID * HID;
            float acc = 0.f;
            for (int m = 0; m < 2 * HID; m++) acc += w1[m] * w2[m * HID + j];
            v = (s == 1) ? ln_g[k] * acc : acc;
        }
        __nv_bfloat16 h = __float2bfloat16(v);
        float rem = v - __bfloat162float(h);
        __nv_bfloat16 lo = __float2bfloat16(rem);
        g_B[(size_t)(s * 2 + 0) * HID * BSTR + j * BSTR + k] = *reinterpret_cast<unsigned short*>(&h);
        g_B[(size_t)(s * 2 + 1) * HID * BSTR + j * BSTR + k] = *reinterpret_cast<unsigned short*>(&lo);
    } else {
        for (int f = 0; f < NNUM; f++) {
            float s = 0.f;
#pragma unroll
            for (int k = 0; k < EMBD; k++)
                s += W_num[f * EMBD + k] * W_in[((NCAT + f) * EMBD + k) * HID + j];
            g_vnum[f * HID + j] = s;
        }
        float bb = b_in[j];
        for (int f = 0; f < NNUM; f++)
#pragma unroll
            for (int k = 0; k < EMBD; k++)
                bb += b_num[f * EMBD + k] * W_in[((NCAT + f) * EMBD + k) * HID + j];
        g_base[j] = bb;
        float d1 = b2[j];
        for (int m = 0; m < 2 * HID; m++) d1 += b1[m] * W2[m * HID + j];
        g_d[j] = d1;
        __shared__ float u[2 * HID];
        for (int m = j; m < 2 * HID; m += HID) {
            float s = 0.f;
            for (int k = 0; k < HID; k++)
                s += ln_b[k] * W1[HID * 2 * HID + k * 2 * HID + m];
            u[m] = s;
        }
        __syncthreads();
        float d2 = b2[HID + j];
        for (int m = 0; m < 2 * HID; m++)
            d2 += (u[m] + b1[2 * HID + m]) * W2[2 * HID * HID + m * HID + j];
        g_d[HID + j] = d2;
        float d3 = b_out[j];
        for (int k = 0; k < HID; k++) d3 += ln_b[HID + k] * W_out[k * HID + j];
        g_d[2 * HID + j] = d3;
    }
}

// ---------------- main fused kernel ----------------
__global__ __launch_bounds__(NTHR, 1)
void main_kernel(const float* __restrict__ x, float* __restrict__ out,
                 int nrows, int ntiles) {
    extern __shared__ __align__(16) char smem[];
    const int t = threadIdx.x;
    const int w = t >> 5;
    const int l = t & 31;
    const int q = l >> 2;      // lane/4
    const int m = l & 3;       // lane%4

    // copy BT matrices and bias vectors
    {
        const float4* src = (const float4*)g_B;
        float4* dst = (float4*)(smem + OB);
        for (int i = t; i < 208896 / 16; i += NTHR) dst[i] = src[i];
        float* dd = (float*)(smem + OD);
        for (int i = t; i < 3 * HID; i += NTHR) dd[i] = g_d[i];
    }
    __syncthreads();

    const unsigned short* BT = (const unsigned short*)(smem + OB);
    float* stg = (float*)(smem + OST);
    const float* dsm = (const float*)(smem + OD);

    const ulonglong2* Tc2 = (const ulonglong2*)g_Tcat;   // row = 32 ulonglong2 (128 f32)
    const int g = l;           // embed: colgroup (cols 4g..4g+3)
    const int rslot = w;       // embed: rows rslot + 8i within 32-row chunk

    // hoisted embed invariants (vnum + base as 4-col vectors)
    ulonglong2 vn[NNUM];
#pragma unroll
    for (int f = 0; f < NNUM; f++)
        vn[f] = __ldg((const ulonglong2*)g_vnum + f * 32 + g);
    const ulonglong2 bbv = __ldg((const ulonglong2*)g_base + g);

    for (int tt = blockIdx.x; tt < ntiles; tt += gridDim.x) {
        const int row0 = tt * 128;

        // ============ embed 4 chunks of 32 rows -> staging -> A fragments ============
        u32 AH[8][4], AL[8][4];
        for (int c = 0; c < 4; c++) {
            const int crow = row0 + 32 * c;
#pragma unroll
            for (int i = 0; i < 4; i++) {
                const int r = rslot + 8 * i;
                const float4* xr4 = (const float4*)(x + (size_t)min(crow + r, nrows - 1) * 40);
                u64 a0 = bbv.x, a1 = bbv.y, b0 = 0ull, b1 = 0ull;
                // categorical: features 4fi..4fi+3 from xr4[fi]
#pragma unroll
                for (int fi = 0; fi < 5; fi++) {
                    float4 xv = __ldg(&xr4[fi]);
                    int i0 = (int)xv.x, i1 = (int)xv.y, i2 = (int)xv.z, i3 = (int)xv.w;
                    ulonglong2 t0 = __ldg(Tc2 + ((4 * fi + 0) * NMOD + i0) * 32 + g);
                    ulonglong2 t1 = __ldg(Tc2 + ((4 * fi + 1) * NMOD + i1) * 32 + g);
                    ulonglong2 t2 = __ldg(Tc2 + ((4 * fi + 2) * NMOD + i2) * 32 + g);
                    ulonglong2 t3 = __ldg(Tc2 + ((4 * fi + 3) * NMOD + i3) * 32 + g);
                    a0 = add2(a0, t0.x); a1 = add2(a1, t0.y);
                    b0 = add2(b0, t1.x); b1 = add2(b1, t1.y);
                    a0 = add2(a0, t2.x); a1 = add2(a1, t2.y);
                    b0 = add2(b0, t3.x); b1 = add2(b1, t3.y);
                }
                // numeric: features 4fi..4fi+3 from xr4[5+fi]
#pragma unroll
                for (int fi = 0; fi < 5; fi++) {
                    float4 xv = __ldg(&xr4[5 + fi]);
                    u64 d0 = dup2(xv.x), d1 = dup2(xv.y), d2 = dup2(xv.z), d3 = dup2(xv.w);
                    a0 = fma2(vn[4 * fi + 0].x, d0, a0); a1 = fma2(vn[4 * fi + 0].y, d0, a1);
                    b0 = fma2(vn[4 * fi + 1].x, d1, b0); b1 = fma2(vn[4 * fi + 1].y, d1, b1);
                    a0 = fma2(vn[4 * fi + 2].x, d2, a0); a1 = fma2(vn[4 * fi + 2].y, d2, a1);
                    b0 = fma2(vn[4 * fi + 3].x, d3, b0); b1 = fma2(vn[4 * fi + 3].y, d3, b1);
                }
                float2 v01 = upk2(add2(a0, b0));
                float2 v23 = upk2(add2(a1, b1));
                *(float4*)&stg[r * SSTR + 4 * g] = make_float4(v01.x, v01.y, v23.x, v23.y);
            }
            __syncthreads();
            // warps 2c, 2c+1 own this chunk's rows: build A fragments
            if ((w >> 1) == c) {
                const int rb = (w & 1) * 16 + q;
#pragma unroll
                for (int kt = 0; kt < 8; kt++) {
                    int c0 = 16 * kt + 2 * m;
                    float2 v00 = *(const float2*)&stg[rb * SSTR + c0];
                    float2 v10 = *(const float2*)&stg[(rb + 8) * SSTR + c0];
                    float2 v01 = *(const float2*)&stg[rb * SSTR + c0 + 8];
                    float2 v11 = *(const float2*)&stg[(rb + 8) * SSTR + c0 + 8];
                    split2(v00.x, v00.y, AH[kt][0], AL[kt][0]);
                    split2(v10.x, v10.y, AH[kt][1], AL[kt][1]);
                    split2(v01.x, v01.y, AH[kt][2], AL[kt][2]);
                    split2(v11.x, v11.y, AH[kt][3], AL[kt][3]);
                }
            }
            __syncthreads();
        }

        // ============ 3 MMA stages, warp-local (R8 structure, verbatim) ============
        float D[16][4];
#pragma unroll 1
        for (int s = 0; s < 3; s++) {
#pragma unroll
            for (int nt = 0; nt < 16; nt++) {
                float2 bv = *(const float2*)&dsm[s * HID + nt * 8 + 2 * m];
                D[nt][0] = bv.x; D[nt][1] = bv.y; D[nt][2] = bv.x; D[nt][3] = bv.y;
            }
            const unsigned short* B0 = BT + (size_t)(s * 2) * HID * BSTR;
            const unsigned short* B1 = B0 + (size_t)HID * BSTR;
#pragma unroll
            for (int kt = 0; kt < 8; kt++) {
                const int koff = kt * 16 + 2 * m;
#pragma unroll
                for (int nt = 0; nt < 16; nt++) {
                    const u32* pb = (const u32*)(B0 + (nt * 8 + q) * BSTR + koff);
                    u32 b0 = pb[0], b1 = pb[4];
                    MMA(D[nt], AH[kt], b0, b1);
                    MMA(D[nt], AL[kt], b0, b1);
                }
#pragma unroll
                for (int nt = 0; nt < 16; nt++) {
                    const u32* pb = (const u32*)(B1 + (nt * 8 + q) * BSTR + koff);
                    u32 b0 = pb[0], b1 = pb[4];
                    MMA(D[nt], AH[kt], b0, b1);
                }
            }

            if (s < 2) {
                // ---- LayerNorm (rows q and q+8): reduce across 4-lane m-group ----
                float s1a = 0.f, s2a = 0.f, s1b = 0.f, s2b = 0.f;
#pragma unroll
                for (int nt = 0; nt < 16; nt++) {
                    s1a += D[nt][0] + D[nt][1];
                    s2a += D[nt][0] * D[nt][0] + D[nt][1] * D[nt][1];
                    s1b += D[nt][2] + D[nt][3];
                    s2b += D[nt][2] * D[nt][2] + D[nt][3] * D[nt][3];
                }
#pragma unroll
                for (int off = 1; off <= 2; off <<= 1) {
                    s1a += __shfl_xor_sync(0xffffffffu, s1a, off);
                    s2a += __shfl_xor_sync(0xffffffffu, s2a, off);
                    s1b += __shfl_xor_sync(0xffffffffu, s1b, off);
                    s2b += __shfl_xor_sync(0xffffffffu, s2b, off);
                }
                const float inv = 1.f / HID;
                float mua = s1a * inv, mub = s1b * inv;
                float rsa = rsqrtf(s2a * inv - mua * mua + 1e-5f);
                float rsb = rsqrtf(s2b * inv - mub * mub + 1e-5f);
                float nma = -mua * rsa, nmb = -mub * rsb;
#pragma unroll
                for (int kt = 0; kt < 8; kt++) {
                    int n0 = 2 * kt, n1 = 2 * kt + 1;
                    split2(D[n0][0] * rsa + nma, D[n0][1] * rsa + nma, AH[kt][0], AL[kt][0]);
                    split2(D[n0][2] * rsb + nmb, D[n0][3] * rsb + nmb, AH[kt][1], AL[kt][1]);
                    split2(D[n1][0] * rsa + nma, D[n1][1] * rsa + nma, AH[kt][2], AL[kt][2]);
                    split2(D[n1][2] * rsb + nmb, D[n1][3] * rsb + nmb, AH[kt][3], AL[kt][3]);
                }
            } else {
                // ---- final store ----
                int ra = row0 + 16 * w + q;
                int rb2 = ra + 8;
#pragma unroll
                for (int nt = 0; nt < 16; nt++) {
                    int col = nt * 8 + 2 * m;
                    if (ra < nrows)
                        *(float2*)&out[(size_t)ra * HID + col] = make_float2(D[nt][0], D[nt][1]);
                    if (rb2 < nrows)
                        *(float2*)&out[(size_t)rb2 * HID + col] = make_float2(D[nt][2], D[nt][3]);
                }
            }
        }
    }
}

// ---------------- launch ----------------
extern "C" void kernel_launch(void* const* d_in, const int* in_sizes, int n_in,
                              void* d_out, int out_size) {
    const float* x     = (const float*)d_in[0];
    const float* emb   = (const float*)d_in[1];
    const float* W_num = (const float*)d_in[2];
    const float* b_num = (const float*)d_in[3];
    const float* W_in  = (const float*)d_in[4];
    const float* b_in  = (const float*)d_in[5];
    const float* W1    = (const float*)d_in[6];
    const float* b1    = (const float*)d_in[7];
    const float* W2    = (const float*)d_in[8];
    const float* b2    = (const float*)d_in[9];
    const float* ln_g  = (const float*)d_in[10];
    const float* ln_b  = (const float*)d_in[11];
    const float* W_out = (const float*)d_in[12];
    const float* b_out = (const float*)d_in[13];
    float* out = (float*)d_out;

    const int nrows  = in_sizes[0] / 40;
    const int ntiles = (nrows + 127) / 128;

    static int smem_set = 0;
    if (!smem_set) {
        cudaFuncSetAttribute(main_kernel, cudaFuncAttributeMaxDynamicSharedMemorySize,
                             SMEM_REQ);
        smem_set = 1;
    }

    pre_all_kernel<<<NCAT * NMOD + 3 * HID + 1, HID>>>(
        emb, W_num, b_num, W_in, b_in, W1, b1, W2, b2, ln_g, ln_b, W_out, b_out);
    main_kernel<<<148, NTHR, SMEM_REQ>>>(x, out, nrows, ntiles);
}